// round 3
// baseline (speedup 1.0000x reference)
#include <cuda_runtime.h>

// Dempster-Shafer combine, algebraically reduced to pure elementwise:
//   out = (a1-1)*(a2-1)/C + a1 + a2 - 1        (denom = 1-K cancels exactly)
//
// R3: persistent grid-stride kernel — exactly one wave (148 SMs x 8 blocks,
// 256 thr), removing ~35 wave transitions / CTA drain cycles. Inner loop
// keeps 2 independent float4 streams in flight per iteration.

#define INV_C (1.0f / 21.0f)

__device__ __forceinline__ float4 ds_combine4(float4 x, float4 y)
{
    float4 r;
    r.x = fmaf((x.x - 1.0f) * (y.x - 1.0f), INV_C, x.x + y.x - 1.0f);
    r.y = fmaf((x.y - 1.0f) * (y.y - 1.0f), INV_C, x.y + y.y - 1.0f);
    r.z = fmaf((x.z - 1.0f) * (y.z - 1.0f), INV_C, x.z + y.z - 1.0f);
    r.w = fmaf((x.w - 1.0f) * (y.w - 1.0f), INV_C, x.w + y.w - 1.0f);
    return r;
}

__global__ void __launch_bounds__(256)
ds_combine_persist(const float4* __restrict__ a1,
                   const float4* __restrict__ a2,
                   float4* __restrict__ out,
                   int n4)
{
    const int stride = gridDim.x * blockDim.x;          // total threads
    int i = blockIdx.x * blockDim.x + threadIdx.x;

    // Main loop: 2 float4 pairs in flight (4 independent LDG.128).
    int i2 = i + stride;
    while (i2 < n4) {
        float4 x0 = a1[i];
        float4 y0 = a2[i];
        float4 x1 = a1[i2];
        float4 y1 = a2[i2];
        out[i]  = ds_combine4(x0, y0);
        out[i2] = ds_combine4(x1, y1);
        i  += 2 * stride;
        i2 += 2 * stride;
    }
    if (i < n4) {
        float4 x0 = a1[i];
        float4 y0 = a2[i];
        out[i] = ds_combine4(x0, y0);
    }
}

extern "C" void kernel_launch(void* const* d_in, const int* in_sizes, int n_in,
                              void* d_out, int out_size)
{
    const float4* a1 = (const float4*)d_in[0];
    const float4* a2 = (const float4*)d_in[1];
    float4* out = (float4*)d_out;

    int n = in_sizes[0];       // 44,040,192 elements (multiple of 4)
    int n4 = n >> 2;           // 11,010,048 float4s

    // One full wave: 152 SMs on GB300, 8 CTAs/SM at 256 thr / 30 regs.
    const int threads = 256;
    const int blocks = 152 * 8;   // 1216 CTAs, single wave

    ds_combine_persist<<<blocks, threads>>>(a1, a2, out, n4);
}

// round 4
// speedup vs baseline: 1.0527x; 1.0527x over previous
#include <cuda_runtime.h>

// Dempster-Shafer combine, algebraically reduced.
//
// Reference computes (per pixel, per class c):
//   b = (alpha-1)/S, u = C/S, K = sum_outer - diag, denom = 1-K
//   out = b_a * S_a + 1  with  b_a = (b1b2 + b1u2 + b2u1)/denom, S_a = C*denom/(u1u2)
// denom cancels; with e = alpha - 1 and b/u = e/C:
//   out = e1*e2/C + e1 + e2 + 1
// Pure elementwise -> layout-independent streaming kernel.
//
// FINAL (R4 = R1): flat float4 kernel, 256 thr, one float4/thread.
// Measured 71.8us kernel / 78.6us harness, 6.82 TB/s (86% of HBM spec) —
// at the mixed read:write stream controller ceiling. Deeper per-thread MLP
// (R2) and persistent one-wave launch (R3) both measured neutral/negative.

#define INV_C (1.0f / 21.0f)

__global__ void __launch_bounds__(256)
ds_combine_kernel(const float4* __restrict__ a1,
                  const float4* __restrict__ a2,
                  float4* __restrict__ out,
                  int n4)
{
    int i = blockIdx.x * blockDim.x + threadIdx.x;
    if (i >= n4) return;

    float4 x = a1[i];
    float4 y = a2[i];
    float4 r;

    // out = (x-1)*(y-1)/C + x + y - 1
    float e1, e2;
    e1 = x.x - 1.0f; e2 = y.x - 1.0f; r.x = fmaf(e1 * e2, INV_C, x.x + y.x - 1.0f);
    e1 = x.y - 1.0f; e2 = y.y - 1.0f; r.y = fmaf(e1 * e2, INV_C, x.y + y.y - 1.0f);
    e1 = x.z - 1.0f; e2 = y.z - 1.0f; r.z = fmaf(e1 * e2, INV_C, x.z + y.z - 1.0f);
    e1 = x.w - 1.0f; e2 = y.w - 1.0f; r.w = fmaf(e1 * e2, INV_C, x.w + y.w - 1.0f);

    out[i] = r;
}

extern "C" void kernel_launch(void* const* d_in, const int* in_sizes, int n_in,
                              void* d_out, int out_size)
{
    const float* a1 = (const float*)d_in[0];
    const float* a2 = (const float*)d_in[1];
    float* out = (float*)d_out;

    int n = in_sizes[0];           // 8*21*512*512 = 44,040,192 (multiple of 4)
    int n4 = n >> 2;               // 11,010,048 float4s

    const int threads = 256;
    int blocks = (n4 + threads - 1) / threads;

    ds_combine_kernel<<<blocks, threads>>>(
        (const float4*)a1, (const float4*)a2, (float4*)out, n4);
}